// round 12
// baseline (speedup 1.0000x reference)
#include <cuda_runtime.h>

// Problem constants
#define B_   16
#define C_   512
#define N_   4096
#define M_   2048
#define TQ   32      // tokens per CTA
#define MC   64      // memory rows per chunk
#define QP   516     // padded smem row stride (floats) for qs/ks
#define STQ  36      // padded stride for transposed score tile St[MC][STQ]
#define NCHUNK (M_ / MC)
#define NTHREADS 256

// smem (floats): qs[TQ][QP] + ks[MC][QP] + St[MC][STQ] + m/l/sc[TQ each]
#define SMEM_FLOATS (TQ*QP + MC*QP + MC*STQ + 3*TQ)

typedef unsigned long long ull;

__device__ __forceinline__ ull fma2(ull a, ull b, ull c) {
    ull d;
    asm("fma.rn.f32x2 %0, %1, %2, %3;" : "=l"(d) : "l"(a), "l"(b), "l"(c));
    return d;
}
__device__ __forceinline__ ull mul2(ull a, ull b) {
    ull d;
    asm("mul.rn.f32x2 %0, %1, %2;" : "=l"(d) : "l"(a), "l"(b));
    return d;
}
__device__ __forceinline__ ull pack2(float x, float y) {
    ull d;
    asm("mov.b64 %0, {%1, %2};" : "=l"(d) : "f"(x), "f"(y));
    return d;
}
__device__ __forceinline__ void unpack2(ull d, float& x, float& y) {
    asm("mov.b64 {%0, %1}, %2;" : "=f"(x), "=f"(y) : "l"(d));
}

__global__ __launch_bounds__(NTHREADS, 1)
void memattn_v3(const float* __restrict__ feat,
                const float* __restrict__ mem,
                float* __restrict__ out)
{
    extern __shared__ float smem[];
    float* qs   = smem;                 // TQ*QP
    float* ks   = qs + TQ * QP;         // MC*QP
    float* St   = ks + MC * QP;         // MC*STQ (scores transposed: [mrow][tok])
    float* m_s  = St + MC * STQ;        // TQ
    float* l_s  = m_s + TQ;             // TQ
    float* sc_s = l_s + TQ;             // TQ

    const int t    = threadIdx.x;
    const int lane = t & 31;
    const int warp = t >> 5;
    const int b    = blockIdx.y;
    const int n0   = blockIdx.x * TQ;

    if (t < TQ) { m_s[t] = -3.0e38f; l_s[t] = 0.0f; }

    // ---- load Q tile: qs[tok][c] = feat[b, c, n0+tok] ----
    const float* fbase = feat + (size_t)b * C_ * N_ + n0;
    #pragma unroll 4
    for (int idx = t; idx < TQ * C_; idx += NTHREADS) {
        int tok = idx & (TQ - 1);
        int c   = idx >> 5;
        qs[tok * QP + c] = fbase[(size_t)c * N_ + tok];
    }

    // ---- GEMM1 mapping: warp=token-group, lane: 8 mrow-groups x 4 kid ----
    const int tg  = warp;          // tokens tg*4 .. +3
    const int mg  = lane & 7;      // mrows mg + 8*j, j=0..7
    const int kid = lane >> 3;     // k in [kid*128, kid*128+128)

    // ---- GEMM2 mapping: 8 tok x 8 col per thread ----
    const int tokg = lane >> 3;                    // tokens tokg*8 .. +7
    const int cb0  = warp * 64 + (lane & 7) * 4;   // cols cb0..+3 and cb0+32..+35

    ull O2[8][4];   // [token][colpair]: 0,1 -> cb0..+3 ; 2,3 -> cb0+32..+35
    #pragma unroll
    for (int a = 0; a < 8; a++)
        #pragma unroll
        for (int c = 0; c < 4; c++) O2[a][c] = 0ull;

    for (int ch = 0; ch < NCHUNK; ch++) {
        __syncthreads();   // prev GEMM2 done with ks/St (and Q-load on ch==0)

        // ---- load K chunk (MC x C) into ks ----
        const float* mbase = mem + (size_t)(ch * MC) * C_;
        #pragma unroll 4
        for (int idx = t; idx < MC * (C_ / 4); idx += NTHREADS) {
            int row = idx >> 7;
            int c4  = idx & 127;
            float4 v = *(const float4*)(mbase + (size_t)row * C_ + c4 * 4);
            *(float4*)(ks + row * QP + c4 * 4) = v;
        }
        __syncthreads();

        // ---- GEMM1: S = Q @ K^T, 4tok x 8mrow tiles, 4-way in-warp k-split ----
        ull acc2[4][8];
        #pragma unroll
        for (int i = 0; i < 4; i++)
            #pragma unroll
            for (int j = 0; j < 8; j++) acc2[i][j] = 0ull;

        const float* qb = qs + (tg * 4) * QP + kid * 128;
        const float* kb = ks + mg * QP + kid * 128;
        #pragma unroll 2
        for (int k = 0; k < 128; k += 4) {
            ulonglong2 qv[4];
            #pragma unroll
            for (int i = 0; i < 4; i++)
                qv[i] = *(const ulonglong2*)(qb + i * QP + k);
            #pragma unroll
            for (int j = 0; j < 8; j++) {
                ulonglong2 kv = *(const ulonglong2*)(kb + j * 8 * QP + k);
                #pragma unroll
                for (int i = 0; i < 4; i++) {
                    acc2[i][j] = fma2(qv[i].x, kv.x, acc2[i][j]);
                    acc2[i][j] = fma2(qv[i].y, kv.y, acc2[i][j]);
                }
            }
        }

        // reduce the 4 k-splits across lane bits 3,4; every lane ends with full sums
        float sred[4][8];
        #pragma unroll
        for (int i = 0; i < 4; i++)
            #pragma unroll
            for (int j = 0; j < 8; j++) {
                float lo, hi; unpack2(acc2[i][j], lo, hi);
                float s = lo + hi;
                s += __shfl_xor_sync(0xffffffffu, s, 8);
                s += __shfl_xor_sync(0xffffffffu, s, 16);
                sred[i][j] = s;
            }
        // kid-lane writes mrow-groups j = 2*kid, 2*kid+1 (partition the duplicates)
        #pragma unroll
        for (int u = 0; u < 2; u++) {
            int jj = kid * 2 + u;
            float4 v = make_float4(sred[0][jj], sred[1][jj], sred[2][jj], sred[3][jj]);
            *(float4*)(St + (mg + 8 * jj) * STQ + tg * 4) = v;
        }
        __syncthreads();

        // ---- online softmax on St columns (per token), 8 lanes/token ----
        {
            int row = t >> 3;          // token
            int g   = t & 7;
            float mx = -3.0e38f;
            #pragma unroll
            for (int j = g; j < MC; j += 8) mx = fmaxf(mx, St[j * STQ + row]);
            mx = fmaxf(mx, __shfl_xor_sync(0xffffffffu, mx, 4));
            mx = fmaxf(mx, __shfl_xor_sync(0xffffffffu, mx, 2));
            mx = fmaxf(mx, __shfl_xor_sync(0xffffffffu, mx, 1));
            float oldm = m_s[row];
            float newm = fmaxf(oldm, mx);
            float sum = 0.0f;
            #pragma unroll
            for (int j = g; j < MC; j += 8) {
                float p = __expf(St[j * STQ + row] - newm);
                St[j * STQ + row] = p;
                sum += p;
            }
            sum += __shfl_xor_sync(0xffffffffu, sum, 4);
            sum += __shfl_xor_sync(0xffffffffu, sum, 2);
            sum += __shfl_xor_sync(0xffffffffu, sum, 1);
            if (g == 0) {
                float sc = __expf(oldm - newm);
                sc_s[row] = sc;
                m_s[row]  = newm;
                l_s[row]  = l_s[row] * sc + sum;
            }
        }
        __syncthreads();

        // ---- GEMM2: O += P @ K  (8 tok x 8 col per thread) ----
        #pragma unroll
        for (int tt = 0; tt < 8; tt++) {
            float sc = sc_s[tokg * 8 + tt];
            ull sc2 = pack2(sc, sc);
            #pragma unroll
            for (int c = 0; c < 4; c++) O2[tt][c] = mul2(O2[tt][c], sc2);
        }
        #pragma unroll 2
        for (int j = 0; j < MC; j++) {
            float4 p0 = *(const float4*)(St + j * STQ + tokg * 8);
            float4 p1 = *(const float4*)(St + j * STQ + tokg * 8 + 4);
            ulonglong2 kva = *(const ulonglong2*)(ks + j * QP + cb0);
            ulonglong2 kvb = *(const ulonglong2*)(ks + j * QP + cb0 + 32);
            float pa[8] = {p0.x, p0.y, p0.z, p0.w, p1.x, p1.y, p1.z, p1.w};
            #pragma unroll
            for (int tt = 0; tt < 8; tt++) {
                ull p2 = pack2(pa[tt], pa[tt]);
                O2[tt][0] = fma2(p2, kva.x, O2[tt][0]);
                O2[tt][1] = fma2(p2, kva.y, O2[tt][1]);
                O2[tt][2] = fma2(p2, kvb.x, O2[tt][2]);
                O2[tt][3] = fma2(p2, kvb.y, O2[tt][3]);
            }
        }
    }

    // ---- epilogue: normalize; thread owns 8 consecutive tokens -> float4 stores ----
    float rl[8];
    #pragma unroll
    for (int tt = 0; tt < 8; tt++) rl[tt] = 1.0f / l_s[tokg * 8 + tt];

    float* obase = out + (size_t)b * C_ * N_ + n0 + tokg * 8;
    #pragma unroll
    for (int cp = 0; cp < 4; cp++) {
        int c0 = cb0 + (cp >> 1) * 32 + (cp & 1) * 2;   // col pair c0, c0+1
        float a[8], bb[8];
        #pragma unroll
        for (int tt = 0; tt < 8; tt++) {
            unpack2(O2[tt][((cp >> 1) << 1) | (cp & 1)], a[tt], bb[tt]);
            a[tt]  *= rl[tt];
            bb[tt] *= rl[tt];
        }
        *(float4*)(obase + (size_t)(c0 + 0) * N_)     = make_float4(a[0], a[1], a[2], a[3]);
        *(float4*)(obase + (size_t)(c0 + 0) * N_ + 4) = make_float4(a[4], a[5], a[6], a[7]);
        *(float4*)(obase + (size_t)(c0 + 1) * N_)     = make_float4(bb[0], bb[1], bb[2], bb[3]);
        *(float4*)(obase + (size_t)(c0 + 1) * N_ + 4) = make_float4(bb[4], bb[5], bb[6], bb[7]);
    }
}

extern "C" void kernel_launch(void* const* d_in, const int* in_sizes, int n_in,
                              void* d_out, int out_size)
{
    const float* feat = (const float*)d_in[0];   // [16, 512, 64, 64]
    const float* mem  = (const float*)d_in[1];   // [2048, 512]
    float* out        = (float*)d_out;
    (void)in_sizes; (void)n_in; (void)out_size;

    const int smem_bytes = SMEM_FLOATS * (int)sizeof(float);   // ~208 KB
    cudaFuncSetAttribute(memattn_v3,
                         cudaFuncAttributeMaxDynamicSharedMemorySize, smem_bytes);

    dim3 grid(N_ / TQ, B_);   // 128 x 16
    memattn_v3<<<grid, NTHREADS, smem_bytes>>>(feat, mem, out);
}

// round 14
// speedup vs baseline: 5.0556x; 5.0556x over previous
#include <cuda_runtime.h>
#include <cuda_bf16.h>
#include <cuda_fp16.h>
#include <cstdint>

#define B_ 16
#define C_ 512
#define N_ 4096
#define M_ 2048

// ---------------- device scratch (allowed: __device__ globals) ----------------
__device__ __nv_bfloat16 g_qh[33554432];   // [B*N, C] bf16 hi   (64 MB)
__device__ __nv_bfloat16 g_ql[33554432];   // [B*N, C] bf16 lo   (64 MB)
__device__ __nv_bfloat16 g_mh[1048576];    // [M, C]  bf16 hi    (2 MB)
__device__ __nv_bfloat16 g_ml[1048576];    // [M, C]  bf16 lo    (2 MB)
__device__ __half        g_mtf[1048576];   // [C, M]  fp16       (2 MB)
__device__ float         g_S[134217728];   // [B*N, M] raw scores (512 MB)
__device__ float         g_rowmax[65536];  // [B*N]

// ---------------- arch feature gate ----------------
// The harness emits a plain compute_103 PTX pass alongside sm_103a; tcgen05 is
// an 'a'-feature. Compile real tcgen05 only when the accelerated target macro
// is defined; emit no-ops otherwise (that fatbin entry never runs on GB300).
#if defined(__CUDA_ARCH_FEAT_SM103_ALL) || defined(__CUDA_ARCH_FEAT_SM100_ALL) || defined(__CUDA_ARCH_FEAT_SM101_ALL)
#define TC_OK 1
#else
#define TC_OK 0
#endif

// ---------------- PTX helpers (sm_103a) ----------------
typedef unsigned long long ull;

__device__ __forceinline__ uint32_t smem_u32(const void* p) {
    uint32_t a;
    asm("{ .reg .u64 t; cvta.to.shared.u64 t, %1; cvt.u32.u64 %0, t; }" : "=r"(a) : "l"(p));
    return a;
}
__device__ __forceinline__ uint32_t elect_one() {
    uint32_t pred;
    asm volatile("{\n\t.reg .pred p;\n\telect.sync _|p, 0xFFFFFFFF;\n\tselp.b32 %0, 1, 0, p;\n\t}" : "=r"(pred));
    return pred;
}

#if TC_OK
#define TCALLOC(sm, n)  asm volatile("tcgen05.alloc.cta_group::1.sync.aligned.shared::cta.b32 [%0], %1;" :: "r"(sm), "r"(n) : "memory")
#define TCDEALLOC(t, n) asm volatile("tcgen05.dealloc.cta_group::1.sync.aligned.b32 %0, %1;" :: "r"(t), "r"(n))
#define TCCOMMIT(mb)    asm volatile("tcgen05.commit.cta_group::1.mbarrier::arrive::one.shared::cluster.b64 [%0];" :: "r"(mb) : "memory")
#define TCFENCE_AFTER() asm volatile("tcgen05.fence::after_thread_sync;" ::: "memory")
#define TCWAIT_LD()     asm volatile("tcgen05.wait::ld.sync.aligned;" ::: "memory")
#else
#define TCALLOC(sm, n)  ((void)0)
#define TCDEALLOC(t, n) ((void)0)
#define TCCOMMIT(mb)    ((void)0)
#define TCFENCE_AFTER() ((void)0)
#define TCWAIT_LD()     ((void)0)
#endif

#define MBINIT(mb, c)   asm volatile("mbarrier.init.shared.b64 [%0], %1;" :: "r"(mb), "r"(c) : "memory")
#define FENCE_ASYNC()   asm volatile("fence.proxy.async.shared::cta;" ::: "memory")

#define MBWAIT(mb, par) do {                                                       \
    uint32_t _m = (mb), _p = (par), _d;                                            \
    asm volatile("{\n\t.reg .pred p;\n\t"                                          \
        "mbarrier.try_wait.parity.acquire.cta.shared::cta.b64 p, [%1], %2;\n\t"    \
        "selp.b32 %0, 1, 0, p;\n\t}" : "=r"(_d) : "r"(_m), "r"(_p) : "memory");    \
    if (!_d) {                                                                     \
        asm volatile("{\n\t.reg .pred P1;\n\t"                                     \
            "WL_%=:\n\t"                                                           \
            "mbarrier.try_wait.parity.acquire.cta.shared::cta.b64 P1, [%0], %1, 0x989680;\n\t" \
            "@P1 bra.uni WD_%=;\n\t"                                               \
            "bra.uni WL_%=;\n\t"                                                   \
            "WD_%=:\n\t}" :: "r"(_m), "r"(_p) : "memory");                         \
    }                                                                              \
} while (0)

#if TC_OK
#define LDTM_X32(r, addr) \
    asm volatile("tcgen05.ld.sync.aligned.32x32b.x32.b32 " \
        "{%0,%1,%2,%3,%4,%5,%6,%7,%8,%9,%10,%11,%12,%13,%14,%15," \
        "%16,%17,%18,%19,%20,%21,%22,%23,%24,%25,%26,%27,%28,%29,%30,%31}, [%32];" \
        : "=r"((r)[0]),"=r"((r)[1]),"=r"((r)[2]),"=r"((r)[3]),"=r"((r)[4]),"=r"((r)[5]),"=r"((r)[6]),"=r"((r)[7]), \
          "=r"((r)[8]),"=r"((r)[9]),"=r"((r)[10]),"=r"((r)[11]),"=r"((r)[12]),"=r"((r)[13]),"=r"((r)[14]),"=r"((r)[15]), \
          "=r"((r)[16]),"=r"((r)[17]),"=r"((r)[18]),"=r"((r)[19]),"=r"((r)[20]),"=r"((r)[21]),"=r"((r)[22]),"=r"((r)[23]), \
          "=r"((r)[24]),"=r"((r)[25]),"=r"((r)[26]),"=r"((r)[27]),"=r"((r)[28]),"=r"((r)[29]),"=r"((r)[30]),"=r"((r)[31]) \
        : "r"(addr))
#else
#define LDTM_X32(r, addr) do { _Pragma("unroll") for (int _z = 0; _z < 32; _z++) (r)[_z] = 0u; (void)(addr); } while (0)
#endif

__device__ __forceinline__ void mma_f16_ss(uint32_t d, uint64_t a, uint64_t b,
                                           uint32_t idesc, uint32_t en) {
#if TC_OK
    asm volatile("{\n\t.reg .pred p;\n\tsetp.ne.u32 p, %4, 0;\n\t"
        "tcgen05.mma.cta_group::1.kind::f16 [%0], %1, %2, %3, {%5,%5,%5,%5}, p;\n\t}"
        :: "r"(d), "l"(a), "l"(b), "r"(idesc), "r"(en), "r"(0u) : "memory");
#else
    (void)d; (void)a; (void)b; (void)idesc; (void)en;
#endif
}

// SW128 swizzle + descriptor (K-major, 128B rows, version=1, SBO=64, LBO=1)
#define SW128(o) ((o) ^ ((((uint32_t)(o)) >> 3) & 0x70u))
static __device__ __forceinline__ uint64_t mk_desc(uint32_t addr) {
    const uint64_t base = (uint64_t(2) << 61) | (uint64_t(1) << 46)
                        | (uint64_t(64) << 32) | (uint64_t(1) << 16);
    return base | ((uint64_t)(addr >> 4) & 0x3FFF);
}

// idesc: dtype=F32(1<<4), atype/btype: BF16=1, F16=0; N>>3 @17; M>>4 @24
#define IDESC_BF16 ((1u<<4) | (1u<<7) | (1u<<10) | ((256u/8)<<17) | ((128u/16)<<24))
#define IDESC_F16  ((1u<<4) |                     ((256u/8)<<17) | ((128u/16)<<24))

// ================= K1a: features [B,C,N] -> qt hi/lo [B*N, C] =================
__global__ void k_prep_feat(const float* __restrict__ feat) {
    __shared__ float tile[32][33];
    int c0 = blockIdx.x * 32, n0 = blockIdx.y * 32, b = blockIdx.z;
    int tx = threadIdx.x & 31, ty = threadIdx.x >> 5;      // 32 x 8
    const float* fb = feat + ((size_t)b * C_ + c0) * N_ + n0;
    #pragma unroll
    for (int i = ty; i < 32; i += 8)
        tile[i][tx] = fb[(size_t)i * N_ + tx];             // tile[c_loc][n_loc]
    __syncthreads();
    int t = threadIdx.x;
    int cp = t & 15;            // c pair index
    int nl = t >> 4;            // token 0..15 (+16)
    #pragma unroll
    for (int k = 0; k < 2; k++) {
        int n = nl + 16 * k;
        float x0 = tile[2 * cp][n], x1 = tile[2 * cp + 1][n];
        __nv_bfloat16 h0 = __float2bfloat16(x0);
        __nv_bfloat16 h1 = __float2bfloat16(x1);
        __nv_bfloat16 l0 = __float2bfloat16(x0 - __bfloat162float(h0));
        __nv_bfloat16 l1 = __float2bfloat16(x1 - __bfloat162float(h1));
        size_t row = (size_t)b * N_ + n0 + n;
        size_t idx = row * (C_ / 2) + (c0 >> 1) + cp;
        ((__nv_bfloat162*)g_qh)[idx] = __nv_bfloat162(h0, h1);
        ((__nv_bfloat162*)g_ql)[idx] = __nv_bfloat162(l0, l1);
    }
}

// ================= K1b: mem split hi/lo (elementwise) =================
__global__ void k_prep_mem(const float* __restrict__ mem) {
    int i = blockIdx.x * blockDim.x + threadIdx.x;   // pair index
    if (i >= M_ * C_ / 2) return;
    float2 v = ((const float2*)mem)[i];
    __nv_bfloat16 h0 = __float2bfloat16(v.x);
    __nv_bfloat16 h1 = __float2bfloat16(v.y);
    __nv_bfloat16 l0 = __float2bfloat16(v.x - __bfloat162float(h0));
    __nv_bfloat16 l1 = __float2bfloat16(v.y - __bfloat162float(h1));
    ((__nv_bfloat162*)g_mh)[i] = __nv_bfloat162(h0, h1);
    ((__nv_bfloat162*)g_ml)[i] = __nv_bfloat162(l0, l1);
}

// ================= K1c: memT fp16 [C, M] =================
__global__ void k_prep_memT(const float* __restrict__ mem) {
    __shared__ float tile[32][33];
    int m0 = blockIdx.x * 32, c0 = blockIdx.y * 32;
    int tx = threadIdx.x & 31, ty = threadIdx.x >> 5;
    #pragma unroll
    for (int i = ty; i < 32; i += 8)
        tile[i][tx] = mem[(size_t)(m0 + i) * C_ + c0 + tx]; // tile[m_loc][c_loc]
    __syncthreads();
    #pragma unroll
    for (int i = ty; i < 32; i += 8)
        g_mtf[(size_t)(c0 + i) * M_ + m0 + tx] = __float2half(tile[tx][i]);
}

// ================= K2: GEMM1 (split-bf16) -> raw S =================
// grid: (8 mtiles of 256, 512 token-tiles of 128), 256 threads
#define SB_AH 1024
#define SB_AL (1024 + 16384)
#define SB_BH (1024 + 32768)
#define SB_BL (1024 + 65536)
#define SB_SMEM 134144    // header 1024 + staging 128*260*4

__global__ __launch_bounds__(256, 1)
void k_gemm1() {
    extern __shared__ char smem[];
    uint32_t sb = smem_u32(smem);
    int t = threadIdx.x, wid = t >> 5, lane = t & 31;
    int mtile = blockIdx.x, ttile = blockIdx.y;

    if (wid == 0) TCALLOC(sb, 512);
    if (t == 0) MBINIT(sb + 16, 1);
    __syncthreads();
    uint32_t tmem;
    asm volatile("ld.shared.b32 %0, [%1];" : "=r"(tmem) : "r"(sb));

    const char* qh = (const char*)g_qh + (size_t)ttile * 128 * 1024;  // row=1024B
    const char* ql = (const char*)g_ql + (size_t)ttile * 128 * 1024;
    const char* mh = (const char*)g_mh + (size_t)mtile * 256 * 1024;
    const char* ml = (const char*)g_ml + (size_t)mtile * 256 * 1024;

    for (int kc = 0; kc < 8; kc++) {
        // A tiles: 128 rows x 128B (hi, lo)
        #pragma unroll
        for (int i = t; i < 1024; i += 256) {
            int row = i >> 3, c16 = i & 7;
            uint32_t off = SW128(row * 128 + c16 * 16);
            size_t g = (size_t)row * 1024 + kc * 128 + c16 * 16;
            *(float4*)(smem + SB_AH + off) = *(const float4*)(qh + g);
            *(float4*)(smem + SB_AL + off) = *(const float4*)(ql + g);
        }
        // B tiles: 256 rows x 128B (hi, lo)
        #pragma unroll
        for (int i = t; i < 2048; i += 256) {
            int row = i >> 3, c16 = i & 7;
            uint32_t off = SW128(row * 128 + c16 * 16);
            size_t g = (size_t)row * 1024 + kc * 128 + c16 * 16;
            *(float4*)(smem + SB_BH + off) = *(const float4*)(mh + g);
            *(float4*)(smem + SB_BL + off) = *(const float4*)(ml + g);
        }
        FENCE_ASYNC();
        __syncthreads();
        if (wid == 0) {
            if (elect_one()) {
                uint64_t ah = mk_desc(sb + SB_AH), al = mk_desc(sb + SB_AL);
                uint64_t bh = mk_desc(sb + SB_BH), bl = mk_desc(sb + SB_BL);
                #pragma unroll
                for (int ks = 0; ks < 4; ks++)
                    mma_f16_ss(tmem, ah + 2 * ks, bh + 2 * ks, IDESC_BF16,
                               (kc == 0 && ks == 0) ? 0u : 1u);
                #pragma unroll
                for (int ks = 0; ks < 4; ks++)
                    mma_f16_ss(tmem, ah + 2 * ks, bl + 2 * ks, IDESC_BF16, 1u);
                #pragma unroll
                for (int ks = 0; ks < 4; ks++)
                    mma_f16_ss(tmem, al + 2 * ks, bh + 2 * ks, IDESC_BF16, 1u);
                TCCOMMIT(sb + 16);
            }
        }
        MBWAIT(sb + 16, kc & 1);
    }
    __syncthreads();
    TCFENCE_AFTER();

    // epilogue: TMEM D[128x256] -> staging -> g_S
    float* St = (float*)(smem + 1024);     // [128][260]
    if (wid < 4) {
        int tok = wid * 32 + lane;
        #pragma unroll 1
        for (int cc = 0; cc < 8; cc++) {
            uint32_t r[32];
            LDTM_X32(r, tmem + cc * 32);
            TCWAIT_LD();
            #pragma unroll
            for (int u = 0; u < 8; u++)
                *(float4*)(St + tok * 260 + cc * 32 + 4 * u) =
                    make_float4(__uint_as_float(r[4*u]),   __uint_as_float(r[4*u+1]),
                                __uint_as_float(r[4*u+2]), __uint_as_float(r[4*u+3]));
        }
    }
    __syncthreads();
    {
        int tok = t >> 1, half = t & 1;
        const float4* src = (const float4*)(St + tok * 260 + half * 128);
        float4* dst = (float4*)(g_S + ((size_t)ttile * 128 + tok) * 2048
                                    + mtile * 256 + half * 128);
        #pragma unroll
        for (int i = 0; i < 32; i++) dst[i] = src[i];
    }
    __syncthreads();
    if (wid == 0) TCDEALLOC(tmem, 512);
}

// ================= K3: row max =================
__global__ void k_rowmax() {
    int row = blockIdx.x * 8 + (threadIdx.x >> 5);
    int lane = threadIdx.x & 31;
    const float4* p = (const float4*)(g_S + (size_t)row * 2048);
    float m = -3.0e38f;
    for (int i = lane; i < 512; i += 32) {
        float4 v = p[i];
        m = fmaxf(m, fmaxf(fmaxf(v.x, v.y), fmaxf(v.z, v.w)));
    }
    #pragma unroll
    for (int s = 16; s > 0; s >>= 1) m = fmaxf(m, __shfl_xor_sync(0xffffffffu, m, s));
    if (lane == 0) g_rowmax[row] = m;
}

// ================= K4: softmax-convert + fp16 GEMM2 =================
// grid: 512 token-tiles, 512 threads
#define SC_A  1024
#define SC_B  (1024 + 16384)
#define SC_ST (1024 + 16384 + 65536)
#define SC_SMEM 134144   // forced to 1 CTA/SM (TMEM needs all 512 cols)

__global__ __launch_bounds__(512, 1)
void k_gemm2(float* __restrict__ out) {
    extern __shared__ char smem[];
    uint32_t sb = smem_u32(smem);
    float* l_s = (float*)(smem + 64);      // [128]
    int t = threadIdx.x, wid = t >> 5, lane = t & 31;
    int tile = blockIdx.x;
    int b = tile >> 5, n0 = (tile & 31) * 128;

    if (wid == 0) TCALLOC(sb, 512);
    if (t == 0) MBINIT(sb + 16, 1);
    __syncthreads();
    uint32_t tmem;
    asm volatile("ld.shared.b32 %0, [%1];" : "=r"(tmem) : "r"(sb));

    const int tok = t >> 2, q = t & 3;
    const float m = g_rowmax[tile * 128 + tok];
    const float thr = m - 18.0f;
    float lsum = 0.0f;
    const float* Srow = g_S + ((size_t)tile * 128 + tok) * 2048;
    const char* mt = (const char*)g_mtf;   // row = 4096 B

    for (int kc = 0; kc < 32; kc++) {
        // B tiles: 512 C-rows x 64 mrows fp16 (two 256-row sub-tiles)
        #pragma unroll
        for (int i = t; i < 4096; i += 512) {
            int row = i >> 3, c16 = i & 7;
            int nt = row >> 8, rl = row & 255;
            uint32_t off = SC_B + nt * 32768 + SW128(rl * 128 + c16 * 16);
            *(float4*)(smem + off) =
                *(const float4*)(mt + (size_t)row * 4096 + kc * 128 + c16 * 16);
        }
        // A tile: P = exp(s - m) fp16 with zero-skip
        {
            const float4* sp = (const float4*)(Srow + kc * 64 + q * 16);
            #pragma unroll
            for (int i = 0; i < 4; i++) {
                float4 s = sp[i];
                float t4 = fmaxf(fmaxf(s.x, s.y), fmaxf(s.z, s.w));
                uint32_t off = SC_A + SW128(tok * 128 + q * 32 + i * 8);
                if (t4 < thr) {
                    *(ull*)(smem + off) = 0ull;
                } else {
                    float p0 = __expf(s.x - m), p1 = __expf(s.y - m);
                    float p2 = __expf(s.z - m), p3 = __expf(s.w - m);
                    lsum += (p0 + p1) + (p2 + p3);
                    __half2 h01 = __float22half2_rn(make_float2(p0, p1));
                    __half2 h23 = __float22half2_rn(make_float2(p2, p3));
                    uint2 u;
                    u.x = *(uint32_t*)&h01;
                    u.y = *(uint32_t*)&h23;
                    *(uint2*)(smem + off) = u;
                }
            }
        }
        FENCE_ASYNC();
        __syncthreads();
        if (wid == 0) {
            if (elect_one()) {
                uint64_t a  = mk_desc(sb + SC_A);
                uint64_t b0 = mk_desc(sb + SC_B);
                uint64_t b1 = mk_desc(sb + SC_B + 32768);
                #pragma unroll
                for (int ks = 0; ks < 4; ks++)
                    mma_f16_ss(tmem,       a + 2 * ks, b0 + 2 * ks, IDESC_F16,
                               (kc == 0 && ks == 0) ? 0u : 1u);
                #pragma unroll
                for (int ks = 0; ks < 4; ks++)
                    mma_f16_ss(tmem + 256, a + 2 * ks, b1 + 2 * ks, IDESC_F16,
                               (kc == 0 && ks == 0) ? 0u : 1u);
                TCCOMMIT(sb + 16);
            }
        }
        MBWAIT(sb + 16, kc & 1);
    }

    // l reduction: lanes tok*4+q are consecutive within warp
    lsum += __shfl_xor_sync(0xffffffffu, lsum, 1);
    lsum += __shfl_xor_sync(0xffffffffu, lsum, 2);
    if (q == 0) l_s[tok] = lsum;
    __syncthreads();
    TCFENCE_AFTER();

    // epilogue: O[128x512] from TMEM, scale 1/l, transpose via staging, store
    if (wid < 4) {
        int tk = wid * 32 + lane;
        float rl = 1.0f / l_s[tk];
        float* St = (float*)(smem + SC_ST) + wid * (32 * 33);
        #pragma unroll 1
        for (int cc = 0; cc < 16; cc++) {
            uint32_t r[32];
            LDTM_X32(r, tmem + cc * 32);
            TCWAIT_LD();
            #pragma unroll
            for (int i = 0; i < 32; i++)
                St[i * 33 + lane] = __uint_as_float(r[i]) * rl;
            __syncwarp();
            // c = cc*32 + lane ; tokens n0 + 32*wid .. +31
            float* dst = out + ((size_t)b * C_ + cc * 32 + lane) * N_ + n0 + wid * 32;
            const float* src = St + lane * 33;
            #pragma unroll
            for (int j = 0; j < 8; j++)
                ((float4*)dst)[j] = make_float4(src[4*j], src[4*j+1], src[4*j+2], src[4*j+3]);
            __syncwarp();
        }
    }
    __syncthreads();
    if (wid == 0) TCDEALLOC(tmem, 512);
}

// ================= launch =================
extern "C" void kernel_launch(void* const* d_in, const int* in_sizes, int n_in,
                              void* d_out, int out_size)
{
    const float* feat = (const float*)d_in[0];   // [16, 512, 64, 64]
    const float* mem  = (const float*)d_in[1];   // [2048, 512]
    float* out        = (float*)d_out;
    (void)in_sizes; (void)n_in; (void)out_size;

    cudaFuncSetAttribute(k_gemm1, cudaFuncAttributeMaxDynamicSharedMemorySize, SB_SMEM);
    cudaFuncSetAttribute(k_gemm2, cudaFuncAttributeMaxDynamicSharedMemorySize, SC_SMEM);

    // prep
    k_prep_feat<<<dim3(C_ / 32, N_ / 32, B_), 256>>>(feat);
    k_prep_mem<<<(M_ * C_ / 2 + 255) / 256, 256>>>(mem);
    k_prep_memT<<<dim3(M_ / 32, C_ / 32), 256>>>(mem);
    // GEMM1: S = Q @ Mem^T  (split bf16)
    k_gemm1<<<dim3(8, 512), 256, SB_SMEM>>>();
    // row max
    k_rowmax<<<65536 / 8, 256>>>();
    // GEMM2: out = softmax(S) @ Mem  (fp16)
    k_gemm2<<<512, 512, SC_SMEM>>>(out);
}

// round 15
// speedup vs baseline: 6.3773x; 1.2614x over previous
#include <cuda_runtime.h>
#include <cuda_bf16.h>
#include <cuda_fp16.h>
#include <cstdint>

#define B_ 16
#define C_ 512
#define N_ 4096
#define M_ 2048

// ---------------- device scratch (allowed: __device__ globals) ----------------
__device__ __nv_bfloat16 g_qh[33554432];   // [B*N, C] bf16 hi   (64 MB)
__device__ __nv_bfloat16 g_ql[33554432];   // [B*N, C] bf16 lo   (64 MB)
__device__ __nv_bfloat16 g_mh[1048576];    // [M, C]  bf16 hi    (2 MB)
__device__ __nv_bfloat16 g_ml[1048576];    // [M, C]  bf16 lo    (2 MB)
__device__ __half        g_mtf[1048576];   // [C, M]  fp16       (2 MB)
__device__ float         g_S[134217728];   // [B*N, M] raw scores (512 MB)
__device__ float         g_rowmax[65536];  // [B*N]

// ---------------- arch feature gate ----------------
#if defined(__CUDA_ARCH_FEAT_SM103_ALL) || defined(__CUDA_ARCH_FEAT_SM100_ALL) || defined(__CUDA_ARCH_FEAT_SM101_ALL)
#define TC_OK 1
#else
#define TC_OK 0
#endif

// ---------------- PTX helpers (sm_103a) ----------------
typedef unsigned long long ull;

__device__ __forceinline__ uint32_t smem_u32(const void* p) {
    uint32_t a;
    asm("{ .reg .u64 t; cvta.to.shared.u64 t, %1; cvt.u32.u64 %0, t; }" : "=r"(a) : "l"(p));
    return a;
}
__device__ __forceinline__ uint32_t elect_one() {
    uint32_t pred;
    asm volatile("{\n\t.reg .pred p;\n\telect.sync _|p, 0xFFFFFFFF;\n\tselp.b32 %0, 1, 0, p;\n\t}" : "=r"(pred));
    return pred;
}

#if TC_OK
#define TCALLOC(sm, n)  asm volatile("tcgen05.alloc.cta_group::1.sync.aligned.shared::cta.b32 [%0], %1;" :: "r"(sm), "r"(n) : "memory")
#define TCDEALLOC(t, n) asm volatile("tcgen05.dealloc.cta_group::1.sync.aligned.b32 %0, %1;" :: "r"(t), "r"(n))
#define TCCOMMIT(mb)    asm volatile("tcgen05.commit.cta_group::1.mbarrier::arrive::one.shared::cluster.b64 [%0];" :: "r"(mb) : "memory")
#define TCFENCE_AFTER() asm volatile("tcgen05.fence::after_thread_sync;" ::: "memory")
#define TCWAIT_LD()     asm volatile("tcgen05.wait::ld.sync.aligned;" ::: "memory")
#else
#define TCALLOC(sm, n)  ((void)0)
#define TCDEALLOC(t, n) ((void)0)
#define TCCOMMIT(mb)    ((void)0)
#define TCFENCE_AFTER() ((void)0)
#define TCWAIT_LD()     ((void)0)
#endif

#define MBINIT(mb, c)   asm volatile("mbarrier.init.shared.b64 [%0], %1;" :: "r"(mb), "r"(c) : "memory")
#define FENCE_ASYNC()   asm volatile("fence.proxy.async.shared::cta;" ::: "memory")

#define MBWAIT(mb, par) do {                                                       \
    uint32_t _m = (mb), _p = (par), _d;                                            \
    asm volatile("{\n\t.reg .pred p;\n\t"                                          \
        "mbarrier.try_wait.parity.acquire.cta.shared::cta.b64 p, [%1], %2;\n\t"    \
        "selp.b32 %0, 1, 0, p;\n\t}" : "=r"(_d) : "r"(_m), "r"(_p) : "memory");    \
    if (!_d) {                                                                     \
        asm volatile("{\n\t.reg .pred P1;\n\t"                                     \
            "WL_%=:\n\t"                                                           \
            "mbarrier.try_wait.parity.acquire.cta.shared::cta.b64 P1, [%0], %1, 0x989680;\n\t" \
            "@P1 bra.uni WD_%=;\n\t"                                               \
            "bra.uni WL_%=;\n\t"                                                   \
            "WD_%=:\n\t}" :: "r"(_m), "r"(_p) : "memory");                         \
    }                                                                              \
} while (0)

#if TC_OK
#define LDTM_X32(r, addr) \
    asm volatile("tcgen05.ld.sync.aligned.32x32b.x32.b32 " \
        "{%0,%1,%2,%3,%4,%5,%6,%7,%8,%9,%10,%11,%12,%13,%14,%15," \
        "%16,%17,%18,%19,%20,%21,%22,%23,%24,%25,%26,%27,%28,%29,%30,%31}, [%32];" \
        : "=r"((r)[0]),"=r"((r)[1]),"=r"((r)[2]),"=r"((r)[3]),"=r"((r)[4]),"=r"((r)[5]),"=r"((r)[6]),"=r"((r)[7]), \
          "=r"((r)[8]),"=r"((r)[9]),"=r"((r)[10]),"=r"((r)[11]),"=r"((r)[12]),"=r"((r)[13]),"=r"((r)[14]),"=r"((r)[15]), \
          "=r"((r)[16]),"=r"((r)[17]),"=r"((r)[18]),"=r"((r)[19]),"=r"((r)[20]),"=r"((r)[21]),"=r"((r)[22]),"=r"((r)[23]), \
          "=r"((r)[24]),"=r"((r)[25]),"=r"((r)[26]),"=r"((r)[27]),"=r"((r)[28]),"=r"((r)[29]),"=r"((r)[30]),"=r"((r)[31]) \
        : "r"(addr))
#else
#define LDTM_X32(r, addr) do { _Pragma("unroll") for (int _z = 0; _z < 32; _z++) (r)[_z] = 0u; (void)(addr); } while (0)
#endif

__device__ __forceinline__ void mma_f16_ss(uint32_t d, uint64_t a, uint64_t b,
                                           uint32_t idesc, uint32_t en) {
#if TC_OK
    asm volatile("{\n\t.reg .pred p;\n\tsetp.ne.u32 p, %4, 0;\n\t"
        "tcgen05.mma.cta_group::1.kind::f16 [%0], %1, %2, %3, {%5,%5,%5,%5}, p;\n\t}"
        :: "r"(d), "l"(a), "l"(b), "r"(idesc), "r"(en), "r"(0u) : "memory");
#else
    (void)d; (void)a; (void)b; (void)idesc; (void)en;
#endif
}

// SW128 swizzle + descriptor (K-major, 128B rows, version=1, SBO=64, LBO=1)
#define SW128(o) ((o) ^ ((((uint32_t)(o)) >> 3) & 0x70u))
static __device__ __forceinline__ uint64_t mk_desc(uint32_t addr) {
    const uint64_t base = (uint64_t(2) << 61) | (uint64_t(1) << 46)
                        | (uint64_t(64) << 32) | (uint64_t(1) << 16);
    return base | ((uint64_t)(addr >> 4) & 0x3FFF);
}

// idesc: dtype=F32(1<<4), atype/btype: BF16=1, F16=0; N>>3 @17; M>>4 @24
#define IDESC_BF16 ((1u<<4) | (1u<<7) | (1u<<10) | ((256u/8)<<17) | ((128u/16)<<24))
#define IDESC_F16  ((1u<<4) |                     ((256u/8)<<17) | ((128u/16)<<24))

// float atomic max (sign-split trick; works for mixed signs, init = -3e38)
__device__ __forceinline__ void atomicMaxFloat(float* addr, float v) {
    if (v >= 0.0f) atomicMax((int*)addr, __float_as_int(v));
    else           atomicMin((unsigned int*)addr, __float_as_uint(v));
}

// ================= K0: init rowmax =================
__global__ void k_init_rowmax() {
    g_rowmax[blockIdx.x * 256 + threadIdx.x] = -3.0e38f;
}

// ================= K1a: features [B,C,N] -> qt hi/lo [B*N, C] =================
__global__ void k_prep_feat(const float* __restrict__ feat) {
    __shared__ float tile[32][33];
    int c0 = blockIdx.x * 32, n0 = blockIdx.y * 32, b = blockIdx.z;
    int tx = threadIdx.x & 31, ty = threadIdx.x >> 5;      // 32 x 8
    const float* fb = feat + ((size_t)b * C_ + c0) * N_ + n0;
    #pragma unroll
    for (int i = ty; i < 32; i += 8)
        tile[i][tx] = fb[(size_t)i * N_ + tx];             // tile[c_loc][n_loc]
    __syncthreads();
    int t = threadIdx.x;
    int cp = t & 15;            // c pair index
    int nl = t >> 4;            // token 0..15 (+16)
    #pragma unroll
    for (int k = 0; k < 2; k++) {
        int n = nl + 16 * k;
        float x0 = tile[2 * cp][n], x1 = tile[2 * cp + 1][n];
        __nv_bfloat16 h0 = __float2bfloat16(x0);
        __nv_bfloat16 h1 = __float2bfloat16(x1);
        __nv_bfloat16 l0 = __float2bfloat16(x0 - __bfloat162float(h0));
        __nv_bfloat16 l1 = __float2bfloat16(x1 - __bfloat162float(h1));
        size_t row = (size_t)b * N_ + n0 + n;
        size_t idx = row * (C_ / 2) + (c0 >> 1) + cp;
        ((__nv_bfloat162*)g_qh)[idx] = __nv_bfloat162(h0, h1);
        ((__nv_bfloat162*)g_ql)[idx] = __nv_bfloat162(l0, l1);
    }
}

// ================= K1b: mem split hi/lo =================
__global__ void k_prep_mem(const float* __restrict__ mem) {
    int i = blockIdx.x * blockDim.x + threadIdx.x;   // pair index
    if (i >= M_ * C_ / 2) return;
    float2 v = ((const float2*)mem)[i];
    __nv_bfloat16 h0 = __float2bfloat16(v.x);
    __nv_bfloat16 h1 = __float2bfloat16(v.y);
    __nv_bfloat16 l0 = __float2bfloat16(v.x - __bfloat162float(h0));
    __nv_bfloat16 l1 = __float2bfloat16(v.y - __bfloat162float(h1));
    ((__nv_bfloat162*)g_mh)[i] = __nv_bfloat162(h0, h1);
    ((__nv_bfloat162*)g_ml)[i] = __nv_bfloat162(l0, l1);
}

// ================= K1c: memT fp16 [C, M] =================
__global__ void k_prep_memT(const float* __restrict__ mem) {
    __shared__ float tile[32][33];
    int m0 = blockIdx.x * 32, c0 = blockIdx.y * 32;
    int tx = threadIdx.x & 31, ty = threadIdx.x >> 5;
    #pragma unroll
    for (int i = ty; i < 32; i += 8)
        tile[i][tx] = mem[(size_t)(m0 + i) * C_ + c0 + tx]; // tile[m_loc][c_loc]
    __syncthreads();
    #pragma unroll
    for (int i = ty; i < 32; i += 8)
        g_mtf[(size_t)(c0 + i) * M_ + m0 + tx] = __float2half(tile[tx][i]);
}

// ================= K2: GEMM1 (split-bf16, 2-stage pipeline) -> raw S + rowmax =================
// grid: (8 mtiles of 256, 512 token-tiles of 128), 256 threads
#define G1_STAGE 98304
#define G1_BASE(s) (1024u + (uint32_t)(s) * G1_STAGE)
#define G1_SMEM (1024 + 2 * G1_STAGE)   // 197632

__global__ __launch_bounds__(256, 1)
void k_gemm1() {
    extern __shared__ char smem[];
    uint32_t sb = smem_u32(smem);
    int t = threadIdx.x, wid = t >> 5, lane = t & 31;
    int mtile = blockIdx.x, ttile = blockIdx.y;

    if (wid == 0) TCALLOC(sb, 512);
    if (t == 0) { MBINIT(sb + 16, 1); MBINIT(sb + 24, 1); }
    __syncthreads();
    uint32_t tmem;
    asm volatile("ld.shared.b32 %0, [%1];" : "=r"(tmem) : "r"(sb));

    const char* qh = (const char*)g_qh + (size_t)ttile * 128 * 1024;  // row=1024B
    const char* ql = (const char*)g_ql + (size_t)ttile * 128 * 1024;
    const char* mh = (const char*)g_mh + (size_t)mtile * 256 * 1024;
    const char* ml = (const char*)g_ml + (size_t)mtile * 256 * 1024;

    // loader for chunk kc into stage s
    auto load_stage = [&](int s, int kc) {
        uint32_t AH = G1_BASE(s), AL = AH + 16384, BH = AH + 32768, BL = AH + 65536;
        #pragma unroll
        for (int i = t; i < 1024; i += 256) {
            int row = i >> 3, c16 = i & 7;
            uint32_t off = SW128(row * 128 + c16 * 16);
            size_t g = (size_t)row * 1024 + (size_t)kc * 128 + c16 * 16;
            *(float4*)(smem + AH + off) = *(const float4*)(qh + g);
            *(float4*)(smem + AL + off) = *(const float4*)(ql + g);
        }
        #pragma unroll
        for (int i = t; i < 2048; i += 256) {
            int row = i >> 3, c16 = i & 7;
            uint32_t off = SW128(row * 128 + c16 * 16);
            size_t g = (size_t)row * 1024 + (size_t)kc * 128 + c16 * 16;
            *(float4*)(smem + BH + off) = *(const float4*)(mh + g);
            *(float4*)(smem + BL + off) = *(const float4*)(ml + g);
        }
    };

    load_stage(0, 0);
    FENCE_ASYNC();
    __syncthreads();

    for (int kc = 0; kc < 8; kc++) {
        int s = kc & 1;
        if (wid == 0) {
            if (elect_one()) {
                uint32_t base = G1_BASE(s);
                uint64_t ah = mk_desc(sb + base), al = mk_desc(sb + base + 16384);
                uint64_t bh = mk_desc(sb + base + 32768), bl = mk_desc(sb + base + 65536);
                #pragma unroll
                for (int ks = 0; ks < 4; ks++)
                    mma_f16_ss(tmem, ah + 2 * ks, bh + 2 * ks, IDESC_BF16,
                               (kc == 0 && ks == 0) ? 0u : 1u);
                #pragma unroll
                for (int ks = 0; ks < 4; ks++)
                    mma_f16_ss(tmem, ah + 2 * ks, bl + 2 * ks, IDESC_BF16, 1u);
                #pragma unroll
                for (int ks = 0; ks < 4; ks++)
                    mma_f16_ss(tmem, al + 2 * ks, bh + 2 * ks, IDESC_BF16, 1u);
                TCCOMMIT(sb + 16 + 8 * s);
            }
        }
        if (kc < 7) {
            if (kc >= 1) {
                // stage s^1 was read by MMA kc-1; wait for it before overwrite
                MBWAIT(sb + 16 + 8 * (s ^ 1), ((kc - 1) >> 1) & 1);
            }
            load_stage(s ^ 1, kc + 1);
            FENCE_ASYNC();
        }
        __syncthreads();
    }
    // drain both mbarriers (MMA 6 on mbar0: 4th completion -> parity 1; MMA 7 on mbar1: parity 1)
    MBWAIT(sb + 16, 1);
    MBWAIT(sb + 24, 1);
    __syncthreads();
    TCFENCE_AFTER();

    // epilogue: TMEM D[128x256] -> staging -> g_S ; fused row max
    float* St = (float*)(smem + 1024);     // [128][260]
    if (wid < 4) {
        int tok = wid * 32 + lane;
        float mx = -3.0e38f;
        #pragma unroll 1
        for (int cc = 0; cc < 8; cc++) {
            uint32_t r[32];
            LDTM_X32(r, tmem + cc * 32);
            TCWAIT_LD();
            #pragma unroll
            for (int u = 0; u < 8; u++) {
                float4 v = make_float4(__uint_as_float(r[4*u]),   __uint_as_float(r[4*u+1]),
                                       __uint_as_float(r[4*u+2]), __uint_as_float(r[4*u+3]));
                mx = fmaxf(mx, fmaxf(fmaxf(v.x, v.y), fmaxf(v.z, v.w)));
                *(float4*)(St + tok * 260 + cc * 32 + 4 * u) = v;
            }
        }
        atomicMaxFloat(&g_rowmax[ttile * 128 + tok], mx);
    }
    __syncthreads();
    {
        int tok = t >> 1, half = t & 1;
        const float4* src = (const float4*)(St + tok * 260 + half * 128);
        float4* dst = (float4*)(g_S + ((size_t)ttile * 128 + tok) * 2048
                                    + mtile * 256 + half * 128);
        #pragma unroll
        for (int i = 0; i < 32; i++) dst[i] = src[i];
    }
    __syncthreads();
    if (wid == 0) TCDEALLOC(tmem, 512);
}

// ================= K4: softmax-convert + fp16 GEMM2 (2-stage pipeline) =================
// grid: 512 token-tiles, 512 threads
#define G2_STAGE 81920   // A 16384 + B 65536
#define G2_BASE(s) (1024u + (uint32_t)(s) * G2_STAGE)
#define G2_SMEM (1024 + 2 * G2_STAGE)   // 164864

__global__ __launch_bounds__(512, 1)
void k_gemm2(float* __restrict__ out) {
    extern __shared__ char smem[];
    uint32_t sb = smem_u32(smem);
    float* l_s = (float*)(smem + 64);      // [128]
    int t = threadIdx.x, wid = t >> 5, lane = t & 31;
    int tile = blockIdx.x;
    int b = tile >> 5, n0 = (tile & 31) * 128;

    if (wid == 0) TCALLOC(sb, 512);
    if (t == 0) { MBINIT(sb + 16, 1); MBINIT(sb + 24, 1); }
    __syncthreads();
    uint32_t tmem;
    asm volatile("ld.shared.b32 %0, [%1];" : "=r"(tmem) : "r"(sb));

    const int tok = t >> 2, q = t & 3;
    const float m = g_rowmax[tile * 128 + tok];
    const float thr = m - 18.0f;
    float lsum = 0.0f;
    const float* Srow = g_S + ((size_t)tile * 128 + tok) * 2048;
    const char* mt = (const char*)g_mtf;   // row = 4096 B

    // producer for chunk kc into stage s (B load + A exp-convert)
    auto produce = [&](int s, int kc) {
        uint32_t A = G2_BASE(s), Bb = A + 16384;
        #pragma unroll
        for (int i = t; i < 4096; i += 512) {
            int row = i >> 3, c16 = i & 7;
            int nt = row >> 8, rl = row & 255;
            uint32_t off = Bb + nt * 32768 + SW128(rl * 128 + c16 * 16);
            *(float4*)(smem + off) =
                *(const float4*)(mt + (size_t)row * 4096 + (size_t)kc * 128 + c16 * 16);
        }
        const float4* sp = (const float4*)(Srow + kc * 64 + q * 16);
        #pragma unroll
        for (int i = 0; i < 4; i++) {
            float4 sv = sp[i];
            float t4 = fmaxf(fmaxf(sv.x, sv.y), fmaxf(sv.z, sv.w));
            uint32_t off = A + SW128(tok * 128 + q * 32 + i * 8);
            if (t4 < thr) {
                *(ull*)(smem + off) = 0ull;
            } else {
                float p0 = __expf(sv.x - m), p1 = __expf(sv.y - m);
                float p2 = __expf(sv.z - m), p3 = __expf(sv.w - m);
                lsum += (p0 + p1) + (p2 + p3);
                __half2 h01 = __float22half2_rn(make_float2(p0, p1));
                __half2 h23 = __float22half2_rn(make_float2(p2, p3));
                uint2 u;
                u.x = *(uint32_t*)&h01;
                u.y = *(uint32_t*)&h23;
                *(uint2*)(smem + off) = u;
            }
        }
    };

    produce(0, 0);
    FENCE_ASYNC();
    __syncthreads();

    for (int kc = 0; kc < 32; kc++) {
        int s = kc & 1;
        if (wid == 0) {
            if (elect_one()) {
                uint32_t base = G2_BASE(s);
                uint64_t a  = mk_desc(sb + base);
                uint64_t b0 = mk_desc(sb + base + 16384);
                uint64_t b1 = mk_desc(sb + base + 16384 + 32768);
                #pragma unroll
                for (int ks = 0; ks < 4; ks++)
                    mma_f16_ss(tmem,       a + 2 * ks, b0 + 2 * ks, IDESC_F16,
                               (kc == 0 && ks == 0) ? 0u : 1u);
                #pragma unroll
                for (int ks = 0; ks < 4; ks++)
                    mma_f16_ss(tmem + 256, a + 2 * ks, b1 + 2 * ks, IDESC_F16,
                               (kc == 0 && ks == 0) ? 0u : 1u);
                TCCOMMIT(sb + 16 + 8 * s);
            }
        }
        if (kc < 31) {
            if (kc >= 1) {
                MBWAIT(sb + 16 + 8 * (s ^ 1), ((kc - 1) >> 1) & 1);
            }
            produce(s ^ 1, kc + 1);
            FENCE_ASYNC();
        }
        __syncthreads();
    }
    // drain: MMA30 on mbar0 (16th completion -> parity 1), MMA31 on mbar1 (parity 1)
    MBWAIT(sb + 16, 1);
    MBWAIT(sb + 24, 1);

    // l reduction: lanes tok*4+q are consecutive within warp
    lsum += __shfl_xor_sync(0xffffffffu, lsum, 1);
    lsum += __shfl_xor_sync(0xffffffffu, lsum, 2);
    if (q == 0) l_s[tok] = lsum;
    __syncthreads();
    TCFENCE_AFTER();

    // epilogue: O[128x512] from TMEM, scale 1/l, transpose via staging, store
    if (wid < 4) {
        int tk = wid * 32 + lane;
        float rl = 1.0f / l_s[tk];
        float* St = (float*)(smem + 1024) + wid * (32 * 33);
        #pragma unroll 1
        for (int cc = 0; cc < 16; cc++) {
            uint32_t r[32];
            LDTM_X32(r, tmem + cc * 32);
            TCWAIT_LD();
            #pragma unroll
            for (int i = 0; i < 32; i++)
                St[i * 33 + lane] = __uint_as_float(r[i]) * rl;
            __syncwarp();
            // c = cc*32 + lane ; tokens n0 + 32*wid .. +31
            float* dst = out + ((size_t)b * C_ + cc * 32 + lane) * N_ + n0 + wid * 32;
            const float* src = St + lane * 33;
            #pragma unroll
            for (int j = 0; j < 8; j++)
                ((float4*)dst)[j] = make_float4(src[4*j], src[4*j+1], src[4*j+2], src[4*j+3]);
            __syncwarp();
        }
    }
    __syncthreads();
    if (wid == 0) TCDEALLOC(tmem, 512);
}

// ================= launch =================
extern "C" void kernel_launch(void* const* d_in, const int* in_sizes, int n_in,
                              void* d_out, int out_size)
{
    const float* feat = (const float*)d_in[0];   // [16, 512, 64, 64]
    const float* mem  = (const float*)d_in[1];   // [2048, 512]
    float* out        = (float*)d_out;
    (void)in_sizes; (void)n_in; (void)out_size;

    cudaFuncSetAttribute(k_gemm1, cudaFuncAttributeMaxDynamicSharedMemorySize, G1_SMEM);
    cudaFuncSetAttribute(k_gemm2, cudaFuncAttributeMaxDynamicSharedMemorySize, G2_SMEM);

    // prep (+ rowmax init)
    k_init_rowmax<<<256, 256>>>();
    k_prep_feat<<<dim3(C_ / 32, N_ / 32, B_), 256>>>(feat);
    k_prep_mem<<<(M_ * C_ / 2 + 255) / 256, 256>>>(mem);
    k_prep_memT<<<dim3(M_ / 32, C_ / 32), 256>>>(mem);
    // GEMM1: S = Q @ Mem^T (split bf16), fused row-max
    k_gemm1<<<dim3(8, 512), 256, G1_SMEM>>>();
    // GEMM2: out = softmax(S) @ Mem (fp16)
    k_gemm2<<<512, 512, G2_SMEM>>>(out);
}

// round 16
// speedup vs baseline: 7.9916x; 1.2531x over previous
#include <cuda_runtime.h>
#include <cuda_bf16.h>
#include <cuda_fp16.h>
#include <cstdint>

#define B_ 16
#define C_ 512
#define N_ 4096
#define M_ 2048

// ---------------- device scratch: tile-contiguous, SW128-pre-swizzled ----------------
// Q hi/lo: [ttile(512)][kc(8)][16384B]  (128 tokens x 128B, swizzled)
__device__ __align__(128) char g_qh2[67108864];
__device__ __align__(128) char g_ql2[67108864];
// Mem hi/lo: [mtile(8)][kc(8)][32768B]  (256 mrows x 128B, swizzled)
__device__ __align__(128) char g_mh2[2097152];
__device__ __align__(128) char g_ml2[2097152];
// MemT fp16 (gemm2 B): [kc(32)][nt(2)][32768B]  (256 C-rows x 128B = 64 mrows fp16, swizzled)
__device__ __align__(128) char g_mtf2[2097152];
__device__ float g_S[134217728];   // [B*N, M] raw scores (512 MB)
__device__ float g_rowmax[65536];  // [B*N]

// ---------------- arch feature gate (tcgen05 only; cp.async.bulk is base sm90) ----------------
#if defined(__CUDA_ARCH_FEAT_SM103_ALL) || defined(__CUDA_ARCH_FEAT_SM100_ALL) || defined(__CUDA_ARCH_FEAT_SM101_ALL)
#define TC_OK 1
#else
#define TC_OK 0
#endif

typedef unsigned long long ull;

__device__ __forceinline__ uint32_t smem_u32(const void* p) {
    uint32_t a;
    asm("{ .reg .u64 t; cvta.to.shared.u64 t, %1; cvt.u32.u64 %0, t; }" : "=r"(a) : "l"(p));
    return a;
}

#if TC_OK
#define TCALLOC(sm, n)  asm volatile("tcgen05.alloc.cta_group::1.sync.aligned.shared::cta.b32 [%0], %1;" :: "r"(sm), "r"(n) : "memory")
#define TCDEALLOC(t, n) asm volatile("tcgen05.dealloc.cta_group::1.sync.aligned.b32 %0, %1;" :: "r"(t), "r"(n))
#define TCCOMMIT(mb)    asm volatile("tcgen05.commit.cta_group::1.mbarrier::arrive::one.shared::cluster.b64 [%0];" :: "r"(mb) : "memory")
#define TCFENCE_AFTER() asm volatile("tcgen05.fence::after_thread_sync;" ::: "memory")
#define TCWAIT_LD()     asm volatile("tcgen05.wait::ld.sync.aligned;" ::: "memory")
#else
#define TCALLOC(sm, n)  ((void)0)
#define TCDEALLOC(t, n) ((void)0)
#define TCCOMMIT(mb)    ((void)0)
#define TCFENCE_AFTER() ((void)0)
#define TCWAIT_LD()     ((void)0)
#endif

#define MBINIT(mb, c)   asm volatile("mbarrier.init.shared.b64 [%0], %1;" :: "r"(mb), "r"(c) : "memory")
#define MBEXPECT(mb, n) asm volatile("mbarrier.arrive.expect_tx.shared.b64 _, [%0], %1;" :: "r"(mb), "r"(n) : "memory")
#define FENCE_ASYNC()   asm volatile("fence.proxy.async.shared::cta;" ::: "memory")

#define MBWAIT(mb, par) do {                                                       \
    uint32_t _m = (mb), _p = (par), _d;                                            \
    asm volatile("{\n\t.reg .pred p;\n\t"                                          \
        "mbarrier.try_wait.parity.acquire.cta.shared::cta.b64 p, [%1], %2;\n\t"    \
        "selp.b32 %0, 1, 0, p;\n\t}" : "=r"(_d) : "r"(_m), "r"(_p) : "memory");    \
    if (!_d) {                                                                     \
        asm volatile("{\n\t.reg .pred P1;\n\t"                                     \
            "WL_%=:\n\t"                                                           \
            "mbarrier.try_wait.parity.acquire.cta.shared::cta.b64 P1, [%0], %1, 0x989680;\n\t" \
            "@P1 bra.uni WD_%=;\n\t"                                               \
            "bra.uni WL_%=;\n\t"                                                   \
            "WD_%=:\n\t}" :: "r"(_m), "r"(_p) : "memory");                         \
    }                                                                              \
} while (0)

// bulk copy gmem -> smem (L2->SMEM direct; completes via mbarrier tx)
__device__ __forceinline__ void bulk_g2s(uint32_t dst, const void* src, uint32_t bytes, uint32_t mbar) {
    asm volatile("cp.async.bulk.shared::cluster.global.mbarrier::complete_tx::bytes [%0], [%1], %2, [%3];"
        :: "r"(dst), "l"(src), "r"(bytes), "r"(mbar) : "memory");
}

#if TC_OK
#define LDTM_X32(r, addr) \
    asm volatile("tcgen05.ld.sync.aligned.32x32b.x32.b32 " \
        "{%0,%1,%2,%3,%4,%5,%6,%7,%8,%9,%10,%11,%12,%13,%14,%15," \
        "%16,%17,%18,%19,%20,%21,%22,%23,%24,%25,%26,%27,%28,%29,%30,%31}, [%32];" \
        : "=r"((r)[0]),"=r"((r)[1]),"=r"((r)[2]),"=r"((r)[3]),"=r"((r)[4]),"=r"((r)[5]),"=r"((r)[6]),"=r"((r)[7]), \
          "=r"((r)[8]),"=r"((r)[9]),"=r"((r)[10]),"=r"((r)[11]),"=r"((r)[12]),"=r"((r)[13]),"=r"((r)[14]),"=r"((r)[15]), \
          "=r"((r)[16]),"=r"((r)[17]),"=r"((r)[18]),"=r"((r)[19]),"=r"((r)[20]),"=r"((r)[21]),"=r"((r)[22]),"=r"((r)[23]), \
          "=r"((r)[24]),"=r"((r)[25]),"=r"((r)[26]),"=r"((r)[27]),"=r"((r)[28]),"=r"((r)[29]),"=r"((r)[30]),"=r"((r)[31]) \
        : "r"(addr))
#else
#define LDTM_X32(r, addr) do { _Pragma("unroll") for (int _z = 0; _z < 32; _z++) (r)[_z] = 0u; (void)(addr); } while (0)
#endif

__device__ __forceinline__ void mma_f16_ss(uint32_t d, uint64_t a, uint64_t b,
                                           uint32_t idesc, uint32_t en) {
#if TC_OK
    asm volatile("{\n\t.reg .pred p;\n\tsetp.ne.u32 p, %4, 0;\n\t"
        "tcgen05.mma.cta_group::1.kind::f16 [%0], %1, %2, %3, {%5,%5,%5,%5}, p;\n\t}"
        :: "r"(d), "l"(a), "l"(b), "r"(idesc), "r"(en), "r"(0u) : "memory");
#else
    (void)d; (void)a; (void)b; (void)idesc; (void)en;
#endif
}

// SW128 swizzle (byte offsets; bits 4-6 ^= bits 7-9, low 4 bits preserved)
#define SW128(o) ((uint32_t)(o) ^ ((((uint32_t)(o)) >> 3) & 0x70u))
static __device__ __forceinline__ uint64_t mk_desc(uint32_t addr) {
    const uint64_t base = (uint64_t(2) << 61) | (uint64_t(1) << 46)
                        | (uint64_t(64) << 32) | (uint64_t(1) << 16);
    return base | ((uint64_t)(addr >> 4) & 0x3FFF);
}

#define IDESC_BF16 ((1u<<4) | (1u<<7) | (1u<<10) | ((256u/8)<<17) | ((128u/16)<<24))
#define IDESC_F16  ((1u<<4) |                     ((256u/8)<<17) | ((128u/16)<<24))

__device__ __forceinline__ void atomicMaxFloat(float* addr, float v) {
    if (v >= 0.0f) atomicMax((int*)addr, __float_as_int(v));
    else           atomicMin((unsigned int*)addr, __float_as_uint(v));
}

// ================= K0: init rowmax =================
__global__ void k_init_rowmax() {
    g_rowmax[blockIdx.x * 256 + threadIdx.x] = -3.0e38f;
}

// ================= K1a: features -> pre-swizzled Q hi/lo tiles =================
__global__ void k_prep_feat(const float* __restrict__ feat) {
    __shared__ float tile[32][33];
    int c0 = blockIdx.x * 32, n0 = blockIdx.y * 32, b = blockIdx.z;
    int tx = threadIdx.x & 31, ty = threadIdx.x >> 5;      // 32 x 8
    const float* fb = feat + ((size_t)b * C_ + c0) * N_ + n0;
    #pragma unroll
    for (int i = ty; i < 32; i += 8)
        tile[i][tx] = fb[(size_t)i * N_ + tx];             // tile[c_loc][n_loc]
    __syncthreads();
    int t = threadIdx.x;
    int cp = t & 15;            // channel pair index within 32-ch block
    int nl = t >> 4;            // token 0..15 (+16)
    #pragma unroll
    for (int k = 0; k < 2; k++) {
        int n = nl + 16 * k;
        float x0 = tile[2 * cp][n], x1 = tile[2 * cp + 1][n];
        __nv_bfloat16 h0 = __float2bfloat16(x0);
        __nv_bfloat16 h1 = __float2bfloat16(x1);
        __nv_bfloat16 l0 = __float2bfloat16(x0 - __bfloat162float(h0));
        __nv_bfloat16 l1 = __float2bfloat16(x1 - __bfloat162float(h1));
        int tokg = b * N_ + n0 + n;
        int tt = tokg >> 7, rowloc = tokg & 127;
        int c = c0 + 2 * cp;
        int kc = c >> 6;
        uint32_t boff = (uint32_t)(c & 63) * 2;
        size_t dst = (size_t)(tt * 8 + kc) * 16384 + SW128(rowloc * 128 + boff);
        *(__nv_bfloat162*)(g_qh2 + dst) = __nv_bfloat162(h0, h1);
        *(__nv_bfloat162*)(g_ql2 + dst) = __nv_bfloat162(l0, l1);
    }
}

// ================= K1b: mem -> pre-swizzled hi/lo tiles =================
__global__ void k_prep_mem(const float* __restrict__ mem) {
    int i = blockIdx.x * blockDim.x + threadIdx.x;   // pair index
    if (i >= M_ * C_ / 2) return;
    float2 v = ((const float2*)mem)[i];
    __nv_bfloat16 h0 = __float2bfloat16(v.x);
    __nv_bfloat16 h1 = __float2bfloat16(v.y);
    __nv_bfloat16 l0 = __float2bfloat16(v.x - __bfloat162float(h0));
    __nv_bfloat16 l1 = __float2bfloat16(v.y - __bfloat162float(h1));
    int m = i >> 8;              // i / 256 pairs per row
    int c = (i & 255) * 2;
    int mtile = m >> 8, rowloc = m & 255;
    int kc = c >> 6;
    uint32_t boff = (uint32_t)(c & 63) * 2;
    size_t dst = (size_t)(mtile * 8 + kc) * 32768 + SW128(rowloc * 128 + boff);
    *(__nv_bfloat162*)(g_mh2 + dst) = __nv_bfloat162(h0, h1);
    *(__nv_bfloat162*)(g_ml2 + dst) = __nv_bfloat162(l0, l1);
}

// ================= K1c: memT fp16 -> pre-swizzled gemm2 B tiles =================
__global__ void k_prep_memT(const float* __restrict__ mem) {
    __shared__ float tile[32][33];   // tile[m_loc][c_loc]
    int m0 = blockIdx.x * 32, c0 = blockIdx.y * 32;
    int tx = threadIdx.x & 31, ty = threadIdx.x >> 5;
    #pragma unroll
    for (int i = ty; i < 32; i += 8)
        tile[i][tx] = mem[(size_t)(m0 + i) * C_ + c0 + tx];
    __syncthreads();
    int t = threadIdx.x;
    if (t < 128) {
        int i = t >> 2;          // c row 0..31
        int j = t & 3;           // 16B unit of 8 mrows
        int c = c0 + i;
        int nt = c >> 8, rowloc = c & 255;
        int kc = m0 >> 6;
        int mb = (m0 & 63) + j * 8;       // byte base = mb*2
        __half h[8];
        #pragma unroll
        for (int k = 0; k < 8; k++) h[k] = __float2half(tile[j * 8 + k][i]);
        size_t dst = (size_t)(kc * 2 + nt) * 32768 + SW128(rowloc * 128 + mb * 2);
        *(uint4*)(g_mtf2 + dst) = *(uint4*)h;
    }
}

// ================= K2: GEMM1 (split-bf16, bulk-copy 2-stage pipeline) =================
// grid: (8 mtiles of 256, 512 token-tiles of 128), 256 threads
// smem: header 1024 | stage0 98304 | stage1 98304  (AH16K AL16K BH32K BL32K)
#define G1_STAGE 98304
#define G1_BASE(s) (1024u + (uint32_t)(s) * G1_STAGE)
#define G1_SMEM (1024 + 2 * G1_STAGE)   // 197632

__global__ __launch_bounds__(256, 1)
void k_gemm1() {
    extern __shared__ char smem[];
    uint32_t sb = smem_u32(smem);
    int t = threadIdx.x, wid = t >> 5, lane = t & 31;
    int mtile = blockIdx.x, ttile = blockIdx.y;

    if (wid == 0) TCALLOC(sb, 512);
    if (t == 0) {
        MBINIT(sb + 16, 1); MBINIT(sb + 24, 1);   // full[0], full[1] (tx)
        MBINIT(sb + 32, 1); MBINIT(sb + 40, 1);   // empty[0], empty[1] (MMA commit)
    }
    __syncthreads();
    uint32_t tmem;
    asm volatile("ld.shared.b32 %0, [%1];" : "=r"(tmem) : "r"(sb));

    const char* qh = g_qh2 + (size_t)ttile * (8 * 16384);
    const char* ql = g_ql2 + (size_t)ttile * (8 * 16384);
    const char* mh = g_mh2 + (size_t)mtile * (8 * 32768);
    const char* ml = g_ml2 + (size_t)mtile * (8 * 32768);

    if (t == 0) {
        // preload stages 0, 1 (chunks 0, 1)
        #pragma unroll
        for (int s = 0; s < 2; s++) {
            uint32_t full = sb + 16 + 8 * s, base = sb + G1_BASE(s);
            MBEXPECT(full, 98304u);
            bulk_g2s(base,         qh + (size_t)s * 16384, 16384u, full);
            bulk_g2s(base + 16384, ql + (size_t)s * 16384, 16384u, full);
            bulk_g2s(base + 32768, mh + (size_t)s * 32768, 32768u, full);
            bulk_g2s(base + 65536, ml + (size_t)s * 32768, 32768u, full);
        }
        for (int kc = 0; kc < 8; kc++) {
            int s = kc & 1;
            uint32_t par = (uint32_t)((kc >> 1) & 1);
            MBWAIT(sb + 16 + 8 * s, par);
            uint32_t base = G1_BASE(s);
            uint64_t ah = mk_desc(sb + base),         al = mk_desc(sb + base + 16384);
            uint64_t bh = mk_desc(sb + base + 32768), bl = mk_desc(sb + base + 65536);
            #pragma unroll
            for (int ks = 0; ks < 4; ks++)
                mma_f16_ss(tmem, ah + 2 * ks, bh + 2 * ks, IDESC_BF16,
                           (kc == 0 && ks == 0) ? 0u : 1u);
            #pragma unroll
            for (int ks = 0; ks < 4; ks++)
                mma_f16_ss(tmem, ah + 2 * ks, bl + 2 * ks, IDESC_BF16, 1u);
            #pragma unroll
            for (int ks = 0; ks < 4; ks++)
                mma_f16_ss(tmem, al + 2 * ks, bh + 2 * ks, IDESC_BF16, 1u);
            TCCOMMIT(sb + 32 + 8 * s);
            if (kc + 2 < 8) {
                MBWAIT(sb + 32 + 8 * s, par);    // MMA kc done -> stage s reusable
                uint32_t full = sb + 16 + 8 * s, sbase = sb + G1_BASE(s);
                int kn = kc + 2;
                MBEXPECT(full, 98304u);
                bulk_g2s(sbase,         qh + (size_t)kn * 16384, 16384u, full);
                bulk_g2s(sbase + 16384, ql + (size_t)kn * 16384, 16384u, full);
                bulk_g2s(sbase + 32768, mh + (size_t)kn * 32768, 32768u, full);
                bulk_g2s(sbase + 65536, ml + (size_t)kn * 32768, 32768u, full);
            }
        }
        // drain: 4th commit per stage -> parity 1
        MBWAIT(sb + 32, 1);
        MBWAIT(sb + 40, 1);
    }
    __syncthreads();
    TCFENCE_AFTER();

    // epilogue: TMEM D[128x256] -> staging -> g_S ; fused row max
    float* St = (float*)(smem + 1024);     // [128][260] (overlaps stage0, mainloop done)
    if (wid < 4) {
        int tok = wid * 32 + lane;
        float mx = -3.0e38f;
        #pragma unroll 1
        for (int cc = 0; cc < 8; cc++) {
            uint32_t r[32];
            LDTM_X32(r, tmem + cc * 32);
            TCWAIT_LD();
            #pragma unroll
            for (int u = 0; u < 8; u++) {
                float4 v = make_float4(__uint_as_float(r[4*u]),   __uint_as_float(r[4*u+1]),
                                       __uint_as_float(r[4*u+2]), __uint_as_float(r[4*u+3]));
                mx = fmaxf(mx, fmaxf(fmaxf(v.x, v.y), fmaxf(v.z, v.w)));
                *(float4*)(St + tok * 260 + cc * 32 + 4 * u) = v;
            }
        }
        atomicMaxFloat(&g_rowmax[ttile * 128 + tok], mx);
    }
    __syncthreads();
    {
        int tok = t >> 1, half = t & 1;
        const float4* src = (const float4*)(St + tok * 260 + half * 128);
        float4* dst = (float4*)(g_S + ((size_t)ttile * 128 + tok) * 2048
                                    + mtile * 256 + half * 128);
        #pragma unroll
        for (int i = 0; i < 32; i++) dst[i] = src[i];
    }
    __syncthreads();
    if (wid == 0) TCDEALLOC(tmem, 512);
}

// ================= K4: softmax-convert + fp16 GEMM2 (bulk B, 2-stage) =================
// grid: 512 token-tiles, 512 threads
// smem: header 1024 | stage s: A 16384 + B 65536 (=81920) x2
#define G2_STAGE 81920
#define G2_BASE(s) (1024u + (uint32_t)(s) * G2_STAGE)
#define G2_SMEM (1024 + 2 * G2_STAGE)   // 164864

__global__ __launch_bounds__(512, 1)
void k_gemm2(float* __restrict__ out) {
    extern __shared__ char smem[];
    uint32_t sb = smem_u32(smem);
    float* l_s = (float*)(smem + 64);      // [128]
    int t = threadIdx.x, wid = t >> 5, lane = t & 31;
    int tile = blockIdx.x;
    int b = tile >> 5, n0 = (tile & 31) * 128;

    if (wid == 0) TCALLOC(sb, 512);
    if (t == 0) {
        MBINIT(sb + 16, 1); MBINIT(sb + 24, 1);   // fullB[0..1] (tx)
        MBINIT(sb + 32, 1); MBINIT(sb + 40, 1);   // mma[0..1]
    }
    __syncthreads();
    uint32_t tmem;
    asm volatile("ld.shared.b32 %0, [%1];" : "=r"(tmem) : "r"(sb));

    const int tok = t >> 2, q = t & 3;
    const float m = g_rowmax[tile * 128 + tok];
    const float thr = m - 18.0f;
    float lsum = 0.0f;
    const float* Srow = g_S + ((size_t)tile * 128 + tok) * 2048;

    // producer: B via bulk (t0), A via exp+STS (all threads)
    auto produce = [&](int s, int kc) {
        uint32_t A = G2_BASE(s);
        if (t == 0) {
            uint32_t full = sb + 16 + 8 * s;
            MBEXPECT(full, 65536u);
            bulk_g2s(sb + A + 16384, g_mtf2 + (size_t)kc * 65536, 65536u, full);
        }
        const float4* sp = (const float4*)(Srow + kc * 64 + q * 16);
        #pragma unroll
        for (int i = 0; i < 4; i++) {
            float4 sv = sp[i];
            float t4 = fmaxf(fmaxf(sv.x, sv.y), fmaxf(sv.z, sv.w));
            uint32_t off = A + SW128(tok * 128 + q * 32 + i * 8);
            if (t4 < thr) {
                *(ull*)(smem + off) = 0ull;
            } else {
                float p0 = __expf(sv.x - m), p1 = __expf(sv.y - m);
                float p2 = __expf(sv.z - m), p3 = __expf(sv.w - m);
                lsum += (p0 + p1) + (p2 + p3);
                __half2 h01 = __float22half2_rn(make_float2(p0, p1));
                __half2 h23 = __float22half2_rn(make_float2(p2, p3));
                uint2 u;
                u.x = *(uint32_t*)&h01;
                u.y = *(uint32_t*)&h23;
                *(uint2*)(smem + off) = u;
            }
        }
    };

    produce(0, 0);
    FENCE_ASYNC();
    __syncthreads();

    for (int kc = 0; kc < 32; kc++) {
        int s = kc & 1;
        if (t == 0) {
            MBWAIT(sb + 16 + 8 * s, (uint32_t)((kc >> 1) & 1));   // B ready
            uint32_t base = G2_BASE(s);
            uint64_t a  = mk_desc(sb + base);
            uint64_t b0 = mk_desc(sb + base + 16384);
            uint64_t b1 = mk_desc(sb + base + 16384 + 32768);
            #pragma unroll
            for (int ks = 0; ks < 4; ks++)
                mma_f16_ss(tmem,       a + 2 * ks, b0 + 2 * ks, IDESC_F16,
                           (kc == 0 && ks == 0) ? 0u : 1u);
            #pragma unroll
            for (int ks = 0; ks < 4; ks++)
                mma_f16_ss(tmem + 256, a + 2 * ks, b1 + 2 * ks, IDESC_F16,
                           (kc == 0 && ks == 0) ? 0u : 1u);
            TCCOMMIT(sb + 32 + 8 * s);
        }
        if (kc < 31) {
            if (kc >= 1) {
                // stage s^1 consumed by MMA kc-1; wait before overwrite (all threads)
                MBWAIT(sb + 32 + 8 * (s ^ 1), (uint32_t)(((kc - 1) >> 1) & 1));
            }
            produce(s ^ 1, kc + 1);
            FENCE_ASYNC();
        }
        __syncthreads();
    }
    // drain: 16th commit per stage -> parity 1 (all threads)
    MBWAIT(sb + 32, 1);
    MBWAIT(sb + 40, 1);

    // l reduction: lanes tok*4+q are consecutive within warp
    lsum += __shfl_xor_sync(0xffffffffu, lsum, 1);
    lsum += __shfl_xor_sync(0xffffffffu, lsum, 2);
    if (q == 0) l_s[tok] = lsum;
    __syncthreads();
    TCFENCE_AFTER();

    // epilogue: O[128x512] from TMEM, scale 1/l, transpose via staging, store
    if (wid < 4) {
        int tk = wid * 32 + lane;
        float rl = 1.0f / l_s[tk];
        float* St = (float*)(smem + 1024) + wid * (32 * 33);
        #pragma unroll 1
        for (int cc = 0; cc < 16; cc++) {
            uint32_t r[32];
            LDTM_X32(r, tmem + cc * 32);
            TCWAIT_LD();
            #pragma unroll
            for (int i = 0; i < 32; i++)
                St[i * 33 + lane] = __uint_as_float(r[i]) * rl;
            __syncwarp();
            float* dst = out + ((size_t)b * C_ + cc * 32 + lane) * N_ + n0 + wid * 32;
            const float* src = St + lane * 33;
            #pragma unroll
            for (int j = 0; j < 8; j++)
                ((float4*)dst)[j] = make_float4(src[4*j], src[4*j+1], src[4*j+2], src[4*j+3]);
            __syncwarp();
        }
    }
    __syncthreads();
    if (wid == 0) TCDEALLOC(tmem, 512);
}

// ================= launch =================
extern "C" void kernel_launch(void* const* d_in, const int* in_sizes, int n_in,
                              void* d_out, int out_size)
{
    const float* feat = (const float*)d_in[0];   // [16, 512, 64, 64]
    const float* mem  = (const float*)d_in[1];   // [2048, 512]
    float* out        = (float*)d_out;
    (void)in_sizes; (void)n_in; (void)out_size;

    cudaFuncSetAttribute(k_gemm1, cudaFuncAttributeMaxDynamicSharedMemorySize, G1_SMEM);
    cudaFuncSetAttribute(k_gemm2, cudaFuncAttributeMaxDynamicSharedMemorySize, G2_SMEM);

    k_init_rowmax<<<256, 256>>>();
    k_prep_feat<<<dim3(C_ / 32, N_ / 32, B_), 256>>>(feat);
    k_prep_mem<<<(M_ * C_ / 2 + 255) / 256, 256>>>(mem);
    k_prep_memT<<<dim3(M_ / 32, C_ / 32), 256>>>(mem);
    k_gemm1<<<dim3(8, 512), 256, G1_SMEM>>>();
    k_gemm2<<<512, 512, G2_SMEM>>>(out);
}